// round 7
// baseline (speedup 1.0000x reference)
#include <cuda_runtime.h>
#include <cuda_bf16.h>

#define B_  16
#define N_  512
#define E_  32
#define HD  64

// Scratch: A[b][k][n] = H[b,n,:] @ W1[:32, k]
//          Bm[b][k][n] = H[b,n,:] @ W1[32:, k] + b1[k]
__device__ float g_A[B_ * HD * N_];
__device__ float g_Bm[B_ * HD * N_];

// ---------------------------------------------------------------------------
// Kernel 1: precompute A and Bm (k-major for coalesced tile loads).
// ---------------------------------------------------------------------------
__global__ void __launch_bounds__(256) precompute_kernel(
    const float* __restrict__ H,
    const float* __restrict__ W1,
    const float* __restrict__ b1)
{
    int which  = blockIdx.x & 1;
    int nChunk = (blockIdx.x >> 1) & 7;
    int b      = blockIdx.x >> 4;

    __shared__ float sW[E_ * HD];
    __shared__ float sH[64 * 33];

    int tid = threadIdx.x;
    const float* Wsrc = W1 + which * E_ * HD;
    #pragma unroll
    for (int p = tid; p < E_ * HD; p += 256) sW[p] = Wsrc[p];

    int nBase = b * N_ + nChunk * 64;
    #pragma unroll
    for (int p = tid; p < 64 * E_; p += 256) {
        int r = p >> 5, c = p & 31;
        sH[r * 33 + c] = H[nBase * E_ + p];
    }
    __syncthreads();

    int nL    = tid & 63;
    int kBase = (tid >> 6) * 16;

    float h[E_];
    #pragma unroll
    for (int e = 0; e < E_; e++) h[e] = sH[nL * 33 + e];

    float* dst = which ? g_Bm : g_A;
    #pragma unroll
    for (int kk = 0; kk < 16; kk++) {
        int k = kBase + kk;
        float acc = which ? b1[k] : 0.0f;
        #pragma unroll
        for (int e = 0; e < E_; e++)
            acc = fmaf(h[e], sW[e * HD + k], acc);
        dst[(b * HD + k) * N_ + nChunk * 64 + nL] = acc;
    }

    cudaTriggerProgrammaticLaunchCompletion();
}

// ---------------------------------------------------------------------------
// packed f32x2 inner step (R2-proven): ADD2; scalar max halves; FFMA2.
// mov.b64 splits/joins are register-coalesced by ptxas.
// ---------------------------------------------------------------------------
__device__ __forceinline__ void pair_step(unsigned long long& acc,
                                          unsigned long long a2,
                                          unsigned long long b2,
                                          unsigned long long w2)
{
    asm("{\n\t"
        ".reg .f32 lo, hi;\n\t"
        ".reg .b64 t, r;\n\t"
        "add.rn.f32x2 t, %1, %2;\n\t"
        "mov.b64 {lo, hi}, t;\n\t"
        "max.f32 lo, lo, 0f00000000;\n\t"
        "max.f32 hi, hi, 0f00000000;\n\t"
        "mov.b64 r, {lo, hi};\n\t"
        "fma.rn.f32x2 %0, r, %3, %0;\n\t"
        "}"
        : "+l"(acc) : "l"(a2), "l"(b2), "l"(w2));
}

__device__ __forceinline__ unsigned long long dup_f32(float x)
{
    unsigned long long d;
    asm("mov.b64 %0, {%1, %1};" : "=l"(d) : "f"(x));
    return d;
}

// ---------------------------------------------------------------------------
// Kernel 2: pair MLP over 64(i) x 32(j) tiles; 1152 blocks, 256 threads.
// Thread (ty 0..31, tx 0..7): 2 rows x 4 cols.
// smem 24.5KB -> ~6 blocks/SM -> ~48 warps/SM (2x previous occupancy).
// ---------------------------------------------------------------------------
__global__ void __launch_bounds__(256, 6) pair_kernel(
    const float* __restrict__ W2,
    const float* __restrict__ b2g,
    float* __restrict__ out)
{
    __shared__ alignas(16) float  As[HD * 64];   // 16 KB  [k][i]
    __shared__ alignas(16) float4 Bs4[HD * 8];   //  8 KB  [k][j/4]
    __shared__ unsigned long long sw2d[HD];
    __shared__ float sb2;

    int tid = threadIdx.x;

    // PDL-overlapped prolog (independent of precompute output)
    if (tid < HD) sw2d[tid] = dup_f32(W2[tid]);
    if (tid == 0) sb2 = b2g[0];

    int b = blockIdx.y;
    int t = blockIdx.x;          // 0..71
    int ti = 0;
    while (t >= (16 - 2 * ti)) { t -= (16 - 2 * ti); ti++; }
    int cj = 2 * ti + t;         // 32-col tile index, cj >= 2*ti

    cudaGridDependencySynchronize();

    // Fill A tile: rows 64*ti..+63, all k  (1024 float4)
    const float4* Ag4 = reinterpret_cast<const float4*>(g_A + (size_t)b * HD * N_ + ti * 64);
    #pragma unroll
    for (int p = 0; p < 4; p++) {
        int idx = tid + p * 256;              // 0..1023
        int k = idx >> 4, q = idx & 15;
        *reinterpret_cast<float4*>(&As[(k << 6) + (q << 2)]) = Ag4[k * (N_ / 4) + q];
    }
    // Fill B tile: cols 32*cj..+31, all k  (512 float4)
    const float4* Bg4 = reinterpret_cast<const float4*>(g_Bm + (size_t)b * HD * N_ + cj * 32);
    #pragma unroll
    for (int p = 0; p < 2; p++) {
        int idx = tid + p * 256;              // 0..511
        int k = idx >> 3, q = idx & 7;
        Bs4[(k << 3) + q] = Bg4[k * (N_ / 4) + q];
    }
    __syncthreads();

    int ty = tid >> 3;           // 0..31 -> i pair
    int tx = tid & 7;            // 0..7  -> j quad

    unsigned long long acc[2][2];
    {
        unsigned long long bi = dup_f32(sb2);
        acc[0][0] = bi; acc[0][1] = bi; acc[1][0] = bi; acc[1][1] = bi;
    }

    const float*      Apf = As + (ty << 1);
    const ulonglong2* Bp  = reinterpret_cast<const ulonglong2*>(Bs4 + tx);

    #pragma unroll 16
    for (int k = 0; k < HD; k++) {
        unsigned long long w2 = sw2d[k];                         // LDS.64 bcast
        float2 a = *reinterpret_cast<const float2*>(Apf + (k << 6));  // LDS.64
        ulonglong2 bv = Bp[k << 3];                              // LDS.128: (b0,b1),(b2,b3)
        unsigned long long a0d = dup_f32(a.x);
        unsigned long long a1d = dup_f32(a.y);
        pair_step(acc[0][0], a0d, bv.x, w2);
        pair_step(acc[0][1], a0d, bv.y, w2);
        pair_step(acc[1][0], a1d, bv.x, w2);
        pair_step(acc[1][1], a1d, bv.y, w2);
    }

    // sigmoid epilogue
    float p[2][4];
    #pragma unroll
    for (int r = 0; r < 2; r++)
        #pragma unroll
        for (int cp = 0; cp < 2; cp++) {
            float lo, hi;
            asm("mov.b64 {%0, %1}, %2;" : "=f"(lo), "=f"(hi) : "l"(acc[r][cp]));
            p[r][cp * 2 + 0] = 1.0f / (1.0f + __expf(-lo));
            p[r][cp * 2 + 1] = 1.0f / (1.0f + __expf(-hi));
        }

    int i0 = ti * 64 + (ty << 1);
    int j0 = cj * 32 + (tx << 2);
    float* outb = out + (size_t)b * N_ * N_;

    if (cj >= 2 * ti + 2) {
        // pure upper tile: all i < j. Write tile (float4) + mirror (float2).
        #pragma unroll
        for (int r = 0; r < 2; r++) {
            float4 v = make_float4(p[r][0], p[r][1], p[r][2], p[r][3]);
            *reinterpret_cast<float4*>(outb + (size_t)(i0 + r) * N_ + j0) = v;
        }
        #pragma unroll
        for (int c = 0; c < 4; c++) {
            float2 v = make_float2(p[0][c], p[1][c]);
            *reinterpret_cast<float2*>(outb + (size_t)(j0 + c) * N_ + i0) = v;
        }
    } else {
        // diagonal-straddling tile: per-element handling
        #pragma unroll
        for (int r = 0; r < 2; r++)
            #pragma unroll
            for (int c = 0; c < 4; c++) {
                int i = i0 + r, j = j0 + c;
                if (i < j) {
                    float v = p[r][c];
                    outb[(size_t)i * N_ + j] = v;
                    outb[(size_t)j * N_ + i] = v;
                } else if (i == j) {
                    outb[(size_t)i * N_ + j] = 0.0f;
                }
            }
    }
}

extern "C" void kernel_launch(void* const* d_in, const int* in_sizes, int n_in,
                              void* d_out, int out_size)
{
    const float* H  = (const float*)d_in[0];   // node_emb [8192, 32]
    const float* W1 = (const float*)d_in[1];   // [64, 64]
    const float* b1 = (const float*)d_in[2];   // [64]
    const float* W2 = (const float*)d_in[3];   // [64]
    const float* b2 = (const float*)d_in[4];   // [1]
    float* out = (float*)d_out;                // [16, 512, 512]

    precompute_kernel<<<256, 256>>>(H, W1, b1);

    // PDL launch: pair_kernel prolog overlaps precompute tail + launch gap
    cudaLaunchConfig_t cfg = {};
    cfg.gridDim  = dim3(72, 16, 1);
    cfg.blockDim = dim3(256, 1, 1);
    cfg.dynamicSmemBytes = 0;
    cfg.stream = 0;
    cudaLaunchAttribute attrs[1];
    attrs[0].id = cudaLaunchAttributeProgrammaticStreamSerialization;
    attrs[0].val.programmaticStreamSerializationAllowed = 1;
    cfg.attrs = attrs;
    cfg.numAttrs = 1;
    cudaLaunchKernelEx(&cfg, pair_kernel, W2, b2, out);
}

// round 8
// speedup vs baseline: 1.0266x; 1.0266x over previous
#include <cuda_runtime.h>
#include <cuda_bf16.h>

#define B_  16
#define N_  512
#define E_  32
#define HD  64

// Scratch: A[b][k][n] = H[b,n,:] @ W1[:32, k]
//          Bm[b][k][n] = H[b,n,:] @ W1[32:, k] + b1[k]
__device__ float g_A[B_ * HD * N_];
__device__ float g_Bm[B_ * HD * N_];

// ---------------------------------------------------------------------------
// Kernel 1: precompute A and Bm (k-major for coalesced tile loads).
// ---------------------------------------------------------------------------
__global__ void __launch_bounds__(256) precompute_kernel(
    const float* __restrict__ H,
    const float* __restrict__ W1,
    const float* __restrict__ b1)
{
    int which  = blockIdx.x & 1;
    int nChunk = (blockIdx.x >> 1) & 7;
    int b      = blockIdx.x >> 4;

    __shared__ float sW[E_ * HD];
    __shared__ float sH[64 * 33];

    int tid = threadIdx.x;
    const float* Wsrc = W1 + which * E_ * HD;
    #pragma unroll
    for (int p = tid; p < E_ * HD; p += 256) sW[p] = Wsrc[p];

    int nBase = b * N_ + nChunk * 64;
    #pragma unroll
    for (int p = tid; p < 64 * E_; p += 256) {
        int r = p >> 5, c = p & 31;
        sH[r * 33 + c] = H[nBase * E_ + p];
    }
    __syncthreads();

    int nL    = tid & 63;
    int kBase = (tid >> 6) * 16;

    float h[E_];
    #pragma unroll
    for (int e = 0; e < E_; e++) h[e] = sH[nL * 33 + e];

    float* dst = which ? g_Bm : g_A;
    #pragma unroll
    for (int kk = 0; kk < 16; kk++) {
        int k = kBase + kk;
        float acc = which ? b1[k] : 0.0f;
        #pragma unroll
        for (int e = 0; e < E_; e++)
            acc = fmaf(h[e], sW[e * HD + k], acc);
        dst[(b * HD + k) * N_ + nChunk * 64 + nL] = acc;
    }

    cudaTriggerProgrammaticLaunchCompletion();
}

// ---------------------------------------------------------------------------
// packed f32x2 inner step, mov-elision-friendly form:
//   ADD2 (asm) -> plain fmaxf on the two halves (compiler/FMNMX, ideally
//   in-place on the pair registers) -> FFMA2 (asm).
// Target SASS: FADD2, FMNMX, FMNMX, FFMA2 — 4 issues / 2 elements.
// ---------------------------------------------------------------------------
__device__ __forceinline__ void pair_step(unsigned long long& acc,
                                          unsigned long long a2,
                                          unsigned long long b2,
                                          unsigned long long w2)
{
    union { unsigned long long u; float2 f; } t;
    asm("add.rn.f32x2 %0, %1, %2;" : "=l"(t.u) : "l"(a2), "l"(b2));
    t.f.x = fmaxf(t.f.x, 0.0f);
    t.f.y = fmaxf(t.f.y, 0.0f);
    asm("fma.rn.f32x2 %0, %1, %2, %0;" : "+l"(acc) : "l"(t.u), "l"(w2));
}

__device__ __forceinline__ unsigned long long dup_f32(float x)
{
    unsigned long long d;
    asm("mov.b64 %0, {%1, %1};" : "=l"(d) : "f"(x));
    return d;
}

// ---------------------------------------------------------------------------
// Kernel 2: pair MLP over 64x64 (i,j) tiles of the upper triangle.
// grid = (36, 16), 256 threads. Thread (ty,tx): 4 rows x 4 cols.
// Per k per thread: 1 LDS.64 bcast (w2) + 3 LDS.128 (A-dup x2, B x1)
// + 8 pair_steps (target 32 compute issues).
// ---------------------------------------------------------------------------
__global__ void __launch_bounds__(256) pair_kernel(
    const float* __restrict__ W2,
    const float* __restrict__ b2g,
    float* __restrict__ out)
{
    __shared__ alignas(16) unsigned long long As_dup[HD * 64];  // 32 KB
    __shared__ alignas(16) float4             Bs4[HD * 16];     // 16 KB
    __shared__ unsigned long long sw2d[HD];
    __shared__ float sb2;

    int tid = threadIdx.x;

    // PDL-overlapped prolog (independent of precompute output)
    if (tid < HD) sw2d[tid] = dup_f32(W2[tid]);
    if (tid == 0) sb2 = b2g[0];

    int b = blockIdx.y;
    int t = blockIdx.x;
    int ti = 0;
    while (t >= (8 - ti)) { t -= (8 - ti); ti++; }
    int tj = ti + t;    // ti <= tj

    cudaGridDependencySynchronize();

    // Fill As_dup: LDG.128 + duplicate + 2x STS.128 per float4
    const float4* Ag4 = reinterpret_cast<const float4*>(g_A + (size_t)b * HD * N_ + ti * 64);
    #pragma unroll
    for (int p = 0; p < 4; p++) {
        int idx = tid + p * 256;          // 0..1023 float4 slots
        int k = idx >> 4, q = idx & 15;
        float4 v = Ag4[k * (N_ / 4) + q];
        ulonglong2* dst = reinterpret_cast<ulonglong2*>(&As_dup[(k << 6) + (q << 2)]);
        dst[0] = make_ulonglong2(dup_f32(v.x), dup_f32(v.y));
        dst[1] = make_ulonglong2(dup_f32(v.z), dup_f32(v.w));
    }

    // Fill Bs4: straight float4 copy
    const float4* Bg4 = reinterpret_cast<const float4*>(g_Bm + (size_t)b * HD * N_ + tj * 64);
    #pragma unroll
    for (int p = 0; p < 4; p++) {
        int idx = tid + p * 256;
        int k = idx >> 4, q = idx & 15;
        Bs4[(k << 4) + q] = Bg4[k * (N_ / 4) + q];
    }
    __syncthreads();

    int ty = tid >> 4, tx = tid & 15;

    unsigned long long acc[4][2];
    {
        unsigned long long bi = dup_f32(sb2);
        #pragma unroll
        for (int r = 0; r < 4; r++) { acc[r][0] = bi; acc[r][1] = bi; }
    }

    const unsigned long long* Ap = As_dup + (ty << 2);
    const ulonglong2*         Bp = reinterpret_cast<const ulonglong2*>(Bs4 + tx);

    #pragma unroll 16
    for (int k = 0; k < HD; k++) {
        unsigned long long w2 = sw2d[k];                                  // LDS.64 bcast
        ulonglong2 bv  = Bp[k << 4];                                      // LDS.128
        ulonglong2 a01 = *reinterpret_cast<const ulonglong2*>(Ap + (k << 6));      // LDS.128
        ulonglong2 a23 = *reinterpret_cast<const ulonglong2*>(Ap + (k << 6) + 2);  // LDS.128
        pair_step(acc[0][0], a01.x, bv.x, w2);
        pair_step(acc[0][1], a01.x, bv.y, w2);
        pair_step(acc[1][0], a01.y, bv.x, w2);
        pair_step(acc[1][1], a01.y, bv.y, w2);
        pair_step(acc[2][0], a23.x, bv.x, w2);
        pair_step(acc[2][1], a23.x, bv.y, w2);
        pair_step(acc[3][0], a23.y, bv.x, w2);
        pair_step(acc[3][1], a23.y, bv.y, w2);
    }

    // sigmoid epilogue
    float p[4][4];
    #pragma unroll
    for (int r = 0; r < 4; r++)
        #pragma unroll
        for (int cp = 0; cp < 2; cp++) {
            float lo, hi;
            asm("mov.b64 {%0, %1}, %2;" : "=f"(lo), "=f"(hi) : "l"(acc[r][cp]));
            p[r][cp * 2 + 0] = 1.0f / (1.0f + __expf(-lo));
            p[r][cp * 2 + 1] = 1.0f / (1.0f + __expf(-hi));
        }

    int i0 = ti * 64 + ty * 4;
    int j0 = tj * 64 + tx * 4;
    float* outb = out + (size_t)b * N_ * N_;

    if (ti != tj) {
        #pragma unroll
        for (int r = 0; r < 4; r++) {
            float4 v = make_float4(p[r][0], p[r][1], p[r][2], p[r][3]);
            *reinterpret_cast<float4*>(outb + (size_t)(i0 + r) * N_ + j0) = v;
        }
        #pragma unroll
        for (int c = 0; c < 4; c++) {
            float4 v = make_float4(p[0][c], p[1][c], p[2][c], p[3][c]);
            *reinterpret_cast<float4*>(outb + (size_t)(j0 + c) * N_ + i0) = v;
        }
    } else {
        #pragma unroll
        for (int r = 0; r < 4; r++)
            #pragma unroll
            for (int c = 0; c < 4; c++) {
                int i = i0 + r, j = j0 + c;
                if (i < j) {
                    float v = p[r][c];
                    outb[(size_t)i * N_ + j] = v;
                    outb[(size_t)j * N_ + i] = v;
                } else if (i == j) {
                    outb[(size_t)i * N_ + j] = 0.0f;
                }
            }
    }
}

extern "C" void kernel_launch(void* const* d_in, const int* in_sizes, int n_in,
                              void* d_out, int out_size)
{
    const float* H  = (const float*)d_in[0];   // node_emb [8192, 32]
    const float* W1 = (const float*)d_in[1];   // [64, 64]
    const float* b1 = (const float*)d_in[2];   // [64]
    const float* W2 = (const float*)d_in[3];   // [64]
    const float* b2 = (const float*)d_in[4];   // [1]
    float* out = (float*)d_out;                // [16, 512, 512]

    precompute_kernel<<<256, 256>>>(H, W1, b1);

    // PDL launch: pair_kernel prolog overlaps precompute tail + launch gap
    cudaLaunchConfig_t cfg = {};
    cfg.gridDim  = dim3(36, 16, 1);
    cfg.blockDim = dim3(256, 1, 1);
    cfg.dynamicSmemBytes = 0;
    cfg.stream = 0;
    cudaLaunchAttribute attrs[1];
    attrs[0].id = cudaLaunchAttributeProgrammaticStreamSerialization;
    attrs[0].val.programmaticStreamSerializationAllowed = 1;
    cfg.attrs = attrs;
    cfg.numAttrs = 1;
    cudaLaunchKernelEx(&cfg, pair_kernel, W2, b2, out);
}